// round 4
// baseline (speedup 1.0000x reference)
#include <cuda_runtime.h>
#include <math.h>
#include <cstdint>
#include <float.h>

#define NB_MAX 256
__device__ float g_partials[NB_MAX];
__device__ unsigned int g_ticket;   // zero-init; last CTA resets it each launch

// 512 threads/CTA = 16 warps. Each CTA owns 128 pred points.
// Warp w covers model-pair slice w (1/16 of pairs); lane holds P=4 pred points.
// Model staged in SMEM pair-interleaved: [x0,x1,y0,y1,z0,z1,w0,w1] (w=|g|^2).
__global__ __launch_bounds__(512, 1)
void cd_kernel(const float* __restrict__ vis,
               const float* __restrict__ tac,
               const float* __restrict__ model,
               const float* __restrict__ scale,
               const float* __restrict__ state,
               float* __restrict__ out,
               int nv, int nt, int nm,
               float wv, float wt, int nb) {
    extern __shared__ float s_model[];        // nm_pairs * 8 floats
    __shared__ float s_par[13];
    __shared__ float s_min[16 * 128];
    __shared__ int s_last;

    const int tid  = threadIdx.x;
    const int lane = tid & 31;
    const int warp = tid >> 5;                // model slice id 0..15
    const int nm_pairs = (nm + 1) >> 1;

    // ---- stage model points (pair-interleaved, with |g|^2) ----
    for (int j = tid; j < nm; j += 512) {
        float gx = model[3 * j + 0];
        float gy = model[3 * j + 1];
        float gz = model[3 * j + 2];
        int p = j >> 1, o = j & 1;
        s_model[p * 8 + 0 + o] = gx;
        s_model[p * 8 + 2 + o] = gy;
        s_model[p * 8 + 4 + o] = gz;
        s_model[p * 8 + 6 + o] = fmaf(gx, gx, fmaf(gy, gy, gz * gz));
    }
    if ((nm & 1) && tid == 0) {
        int p = nm >> 1;
        s_model[p * 8 + 1] = 0.f; s_model[p * 8 + 3] = 0.f;
        s_model[p * 8 + 5] = 0.f; s_model[p * 8 + 7] = FLT_MAX * 0.5f;
    }

    // ---- fused setup: R = Rz@Ry@Rx, t, 1/scale ----
    if (tid == 0) {
        float ox = state[3], oy = state[4], oz = state[5];
        float sx = sinf(ox), cx = cosf(ox);
        float sy = sinf(oy), cy = cosf(oy);
        float sz = sinf(oz), cz = cosf(oz);
        s_par[0] = cz * cy;
        s_par[1] = cz * sy * sx - sz * cx;
        s_par[2] = cz * sy * cx + sz * sx;
        s_par[3] = sz * cy;
        s_par[4] = sz * sy * sx + cz * cx;
        s_par[5] = sz * sy * cx - cz * sx;
        s_par[6] = -sy;
        s_par[7] = cy * sx;
        s_par[8] = cy * cx;
        s_par[9]  = state[0];
        s_par[10] = state[1];
        s_par[11] = state[2];
        s_par[12] = 1.0f / scale[0];
    }
    __syncthreads();

    const int ntot = nv + nt;

    // ---- per-thread transform of P=4 pred points ----
    float a[4], wgt[4];
    uint64_t qx2[4], qy2[4], qz2[4];
    #pragma unroll
    for (int k = 0; k < 4; k++) {
        int pidx = k * 32 + lane;                 // point slot in CTA
        int i = blockIdx.x * 128 + pidx;
        float px = 0.f, py = 0.f, pz = 0.f;
        wgt[k] = 0.f;
        if (i < ntot) {
            const float* src; int idx;
            if (i < nv) { src = vis; idx = i;      wgt[k] = wv; }
            else        { src = tac; idx = i - nv; wgt[k] = wt; }
            float vx = src[3 * idx + 0] - s_par[9];
            float vy = src[3 * idx + 1] - s_par[10];
            float vz = src[3 * idx + 2] - s_par[11];
            float inv_s = s_par[12];
            px = (vx * s_par[0] + vy * s_par[3] + vz * s_par[6]) * inv_s;
            py = (vx * s_par[1] + vy * s_par[4] + vz * s_par[7]) * inv_s;
            pz = (vx * s_par[2] + vy * s_par[5] + vz * s_par[8]) * inv_s;
        }
        a[k] = fmaf(px, px, fmaf(py, py, pz * pz));
        float qx = -2.0f * px, qy = -2.0f * py, qz = -2.0f * pz;
        asm("mov.b64 %0, {%1,%1};" : "=l"(qx2[k]) : "f"(qx));
        asm("mov.b64 %0, {%1,%1};" : "=l"(qy2[k]) : "f"(qy));
        asm("mov.b64 %0, {%1,%1};" : "=l"(qz2[k]) : "f"(qz));
    }

    // ---- this warp's slice of model pairs ----
    const int pairs_per = (nm_pairs + 15) >> 4;
    int pb = warp * pairs_per; if (pb > nm_pairs) pb = nm_pairs;
    int pe = pb + pairs_per;   if (pe > nm_pairs) pe = nm_pairs;

    uint32_t addr;
    {
        uint64_t a64;
        asm("cvta.to.shared.u64 %0, %1;" : "=l"(a64) : "l"(s_model + (size_t)pb * 8));
        addr = (uint32_t)a64;
    }

    float m_lo[4], m_hi[4];
    #pragma unroll
    for (int k = 0; k < 4; k++) { m_lo[k] = FLT_MAX; m_hi[k] = FLT_MAX; }

    // two pairs per iteration: two independent LDS.128 batches in flight
    int p = pb;
    for (; p + 2 <= pe; p += 2, addr += 64) {
        uint64_t x2a, y2a, z2a, w2a, x2b, y2b, z2b, w2b;
        asm("ld.shared.v2.u64 {%0,%1}, [%2];"    : "=l"(x2a), "=l"(y2a) : "r"(addr));
        asm("ld.shared.v2.u64 {%0,%1}, [%2+16];" : "=l"(z2a), "=l"(w2a) : "r"(addr));
        asm("ld.shared.v2.u64 {%0,%1}, [%2+32];" : "=l"(x2b), "=l"(y2b) : "r"(addr));
        asm("ld.shared.v2.u64 {%0,%1}, [%2+48];" : "=l"(z2b), "=l"(w2b) : "r"(addr));
        #pragma unroll
        for (int k = 0; k < 4; k++) {
            uint64_t d2;
            asm("fma.rn.f32x2 %0, %1, %2, %3;" : "=l"(d2) : "l"(qz2[k]), "l"(z2a), "l"(w2a));
            asm("fma.rn.f32x2 %0, %1, %2, %0;" : "+l"(d2) : "l"(qy2[k]), "l"(y2a));
            asm("fma.rn.f32x2 %0, %1, %2, %0;" : "+l"(d2) : "l"(qx2[k]), "l"(x2a));
            float dlo, dhi;
            asm("mov.b64 {%0,%1}, %2;" : "=f"(dlo), "=f"(dhi) : "l"(d2));
            m_lo[k] = fminf(m_lo[k], dlo);
            m_hi[k] = fminf(m_hi[k], dhi);
        }
        #pragma unroll
        for (int k = 0; k < 4; k++) {
            uint64_t d2;
            asm("fma.rn.f32x2 %0, %1, %2, %3;" : "=l"(d2) : "l"(qz2[k]), "l"(z2b), "l"(w2b));
            asm("fma.rn.f32x2 %0, %1, %2, %0;" : "+l"(d2) : "l"(qy2[k]), "l"(y2b));
            asm("fma.rn.f32x2 %0, %1, %2, %0;" : "+l"(d2) : "l"(qx2[k]), "l"(x2b));
            float dlo, dhi;
            asm("mov.b64 {%0,%1}, %2;" : "=f"(dlo), "=f"(dhi) : "l"(d2));
            m_lo[k] = fminf(m_lo[k], dlo);
            m_hi[k] = fminf(m_hi[k], dhi);
        }
    }
    for (; p < pe; ++p, addr += 32) {
        uint64_t x2, y2, z2, w2;
        asm("ld.shared.v2.u64 {%0,%1}, [%2];"    : "=l"(x2), "=l"(y2) : "r"(addr));
        asm("ld.shared.v2.u64 {%0,%1}, [%2+16];" : "=l"(z2), "=l"(w2) : "r"(addr));
        #pragma unroll
        for (int k = 0; k < 4; k++) {
            uint64_t d2;
            asm("fma.rn.f32x2 %0, %1, %2, %3;" : "=l"(d2) : "l"(qz2[k]), "l"(z2), "l"(w2));
            asm("fma.rn.f32x2 %0, %1, %2, %0;" : "+l"(d2) : "l"(qy2[k]), "l"(y2));
            asm("fma.rn.f32x2 %0, %1, %2, %0;" : "+l"(d2) : "l"(qx2[k]), "l"(x2));
            float dlo, dhi;
            asm("mov.b64 {%0,%1}, %2;" : "=f"(dlo), "=f"(dhi) : "l"(d2));
            m_lo[k] = fminf(m_lo[k], dlo);
            m_hi[k] = fminf(m_hi[k], dhi);
        }
    }

    #pragma unroll
    for (int k = 0; k < 4; k++)
        s_min[warp * 128 + k * 32 + lane] = fminf(m_lo[k], m_hi[k]);
    __syncthreads();

    // ---- per-CTA reduction (warp 0) ----
    if (warp == 0) {
        float vsum = 0.0f;
        #pragma unroll
        for (int k = 0; k < 4; k++) {
            int pidx = k * 32 + lane;
            float m = s_min[pidx];
            #pragma unroll
            for (int s = 1; s < 16; s++)
                m = fminf(m, s_min[s * 128 + pidx]);
            int i = blockIdx.x * 128 + pidx;
            if (i < ntot) vsum += (a[k] + m) * wgt[k];
        }
        #pragma unroll
        for (int o = 16; o > 0; o >>= 1)
            vsum += __shfl_down_sync(0xffffffffu, vsum, o);
        if (lane == 0) g_partials[blockIdx.x] = vsum;
    }
    __syncthreads();

    // ---- last-CTA-done fused final reduction ----
    if (tid == 0) {
        __threadfence();
        unsigned int t = atomicAdd(&g_ticket, 1u);
        s_last = (t == (unsigned int)(nb - 1)) ? 1 : 0;
    }
    __syncthreads();
    if (s_last && warp == 0) {
        float s = 0.0f;
        for (int b = lane; b < nb; b += 32)
            s += *((volatile float*)&g_partials[b]);
        #pragma unroll
        for (int o = 16; o > 0; o >>= 1)
            s += __shfl_down_sync(0xffffffffu, s, o);
        if (lane == 0) {
            out[0] = s;
            g_ticket = 0;   // reset for next graph replay
        }
    }
}

extern "C" void kernel_launch(void* const* d_in, const int* in_sizes, int n_in,
                              void* d_out, int out_size) {
    const float* vis   = (const float*)d_in[0];  // visual_points  (16384,3)
    const float* tac   = (const float*)d_in[1];  // tactile_points (2048,3)
    const float* model = (const float*)d_in[2];  // model_points   (8192,3)
    const float* scale = (const float*)d_in[3];  // scalar
    const float* state = (const float*)d_in[4];  // (6,)
    float* out = (float*)d_out;

    int nv = in_sizes[0] / 3;
    int nt = in_sizes[1] / 3;
    int nm = in_sizes[2] / 3;

    int ntot = nv + nt;
    int nb = (ntot + 127) / 128;               // 144 for default shapes
    if (nb > NB_MAX) nb = NB_MAX;

    int nm_pairs = (nm + 1) / 2;
    size_t smem = (size_t)nm_pairs * 32;       // 131072 B for nm=8192
    cudaFuncSetAttribute(cd_kernel, cudaFuncAttributeMaxDynamicSharedMemorySize,
                         (int)smem);

    float wv = 1.0f / (float)nv;
    float wt = 0.1f / (float)nt;

    cd_kernel<<<nb, 512, smem>>>(vis, tac, model, scale, state, out,
                                 nv, nt, nm, wv, wt, nb);
}